// round 5
// baseline (speedup 1.0000x reference)
#include <cuda_runtime.h>
#include <cstdint>

// Problem shape (fixed): x:(32,512,64,64) f32, weight:(1,1,3,3), k=256
#define BB 32
#define NN 512
#define HH 64
#define WW 64
#define IMG_ELEMS (HH * WW)          // 4096

// Scratch (no cudaMalloc allowed)
__device__ float2 g_scores[BB * NN];
__device__ int    g_order[BB * NN];

// ---------------------------------------------------------------------------
// Phase 1: warp-per-image conv score. Lane li owns cols 2li,2li+1.
// Rows in chunks of 8, DOUBLE-BUFFERED: chunk c+1's 8 LDG.64 are in flight
// while chunk c computes. Horizontal neighbors via SHFL; vertical window in
// registers. Per-row Fast2Sum fold keeps ordering exact vs ~0.2 score gaps.
// grid = B*N/8, block = 256 (8 warps = 8 images).
// ---------------------------------------------------------------------------
__global__ __launch_bounds__(256) void score_kernel(
    const float* __restrict__ x, const float* __restrict__ w,
    float2* __restrict__ scores)
{
    const int li   = threadIdx.x & 31;
    const int img  = blockIdx.x * 8 + (threadIdx.x >> 5);
    const bool tail = (li == 31);                 // cols 62,63: invalid outputs

    const float wc = w[0];   // corners
    const float wE = w[1];   // edges
    const float wm = w[4];   // center

    const float2* b2 = reinterpret_cast<const float2*>(
        x + (size_t)img * IMG_ELEMS) + li;        // 32 float2 per row

    float Ha1[2], Hm1[2], Ha2[2], Hm2[2];
    float s = 0.f, e = 0.f;

    float2 va[8], vb[8];

    // preload chunk 0
#pragma unroll
    for (int i = 0; i < 8; i++) va[i] = b2[i * 32];

    // prime window with rows 0,1
    {
        float nx = __shfl_down_sync(0xffffffffu, va[0].x, 1);
        float ny = __shfl_down_sync(0xffffffffu, va[0].y, 1);
        Ha2[0] = va[0].x + nx;  Hm2[0] = va[0].y;
        Ha2[1] = va[0].y + ny;  Hm2[1] = nx;
        nx = __shfl_down_sync(0xffffffffu, va[1].x, 1);
        ny = __shfl_down_sync(0xffffffffu, va[1].y, 1);
        Ha1[0] = va[1].x + nx;  Hm1[0] = va[1].y;
        Ha1[1] = va[1].y + ny;  Hm1[1] = nx;
    }

#define DO_ROW(vv)                                                          \
    {                                                                       \
        float nx = __shfl_down_sync(0xffffffffu, (vv).x, 1);                \
        float ny = __shfl_down_sync(0xffffffffu, (vv).y, 1);                \
        float Hac0 = (vv).x + nx, Hmc0 = (vv).y;                            \
        float Hac1 = (vv).y + ny, Hmc1 = nx;                                \
        float s1a = Ha2[0] + Hac0;                                          \
        float s2a = (Hm2[0] + Hmc0) + Ha1[0];                               \
        float vra = fmaf(wc, s1a, fmaf(wE, s2a, wm * Hm1[0]));              \
        float s1b = Ha2[1] + Hac1;                                          \
        float s2b = (Hm2[1] + Hmc1) + Ha1[1];                               \
        float vrb = fmaf(wc, s1b, fmaf(wE, s2b, wm * Hm1[1]));              \
        float row = fabsf(vra) + fabsf(vrb);                                \
        if (tail) row = 0.f;                                                \
        float tt  = __fadd_rn(s, row);                                      \
        e = __fadd_rn(e, __fadd_rn(__fsub_rn(s, tt), row));                 \
        s = tt;                                                             \
        Ha2[0] = Ha1[0]; Hm2[0] = Hm1[0]; Ha1[0] = Hac0; Hm1[0] = Hmc0;     \
        Ha2[1] = Ha1[1]; Hm2[1] = Hm1[1]; Ha1[1] = Hac1; Hm1[1] = Hmc1;     \
    }

#pragma unroll
    for (int c = 0; c < 8; c++) {
        float2* cur = (c & 1) ? vb : va;
        float2* nxt = (c & 1) ? va : vb;
        if (c < 7) {
#pragma unroll
            for (int i = 0; i < 8; i++) nxt[i] = b2[((c + 1) * 8 + i) * 32];
        }
#pragma unroll
        for (int i = (c == 0 ? 2 : 0); i < 8; i++) DO_ROW(cur[i]);
    }
#undef DO_ROW

    // Full-warp double-float reduction (exact TwoSum)
#pragma unroll
    for (int off = 16; off; off >>= 1) {
        float s2 = __shfl_down_sync(0xffffffffu, s, off);
        float e2 = __shfl_down_sync(0xffffffffu, e, off);
        float tt  = __fadd_rn(s, s2);
        float z   = __fsub_rn(tt, s);
        float err = __fadd_rn(__fsub_rn(s, __fsub_rn(tt, z)), __fsub_rn(s2, z));
        e = __fadd_rn(__fadd_rn(e, e2), err);
        s = tt;
    }

    if (li == 0) {
        float h = __fadd_rn(s, e);
        float l = __fadd_rn(__fsub_rn(s, h), e);
        scores[img] = make_float2(h, l);
    }
}

// ---------------------------------------------------------------------------
// Phase 2: exact top-k ranking per batch (descending, ties -> lower index first)
// ---------------------------------------------------------------------------
__global__ __launch_bounds__(NN) void topk_kernel(
    const float2* __restrict__ scores, int* __restrict__ order, int k)
{
    __shared__ float2 sc[NN];
    const int b = blockIdx.x;
    const int n = threadIdx.x;
    sc[n] = scores[b * NN + n];
    __syncthreads();

    const float2 mine = sc[n];
    int rank = 0;
#pragma unroll 8
    for (int m = 0; m < NN; m++) {
        float2 o = sc[m];
        bool better = (o.x > mine.x) ||
                      (o.x == mine.x && (o.y > mine.y ||
                                         (o.y == mine.y && m < n)));
        rank += better;
    }
    if (rank < k) order[b * k + rank] = n;
}

// ---------------------------------------------------------------------------
// Phase 3: gather, 2 images per 256-thread block. Both index loads issued
// up front, then all 8 data loads (2 imgs x 4 float4) in flight before any
// store. Blocks run reversed so gather hits the x tail still resident in L2.
// grid = B*k/2 blocks.
// ---------------------------------------------------------------------------
__global__ __launch_bounds__(256) void gather_kernel(
    const float* __restrict__ x, const int* __restrict__ order,
    float* __restrict__ out, int k)
{
    const int pair = gridDim.x - 1 - blockIdx.x;  // reversed for L2 reuse
    const int bj0  = pair * 2;
    const int bj1  = bj0 + 1;
    const int n0   = __ldg(&order[bj0]);
    const int n1   = __ldg(&order[bj1]);
    const int b    = bj0 / k;                      // bj0,bj1 same batch (k even)

    const float4* s0 = reinterpret_cast<const float4*>(
        x + ((size_t)(b * NN + n0)) * IMG_ELEMS);
    const float4* s1 = reinterpret_cast<const float4*>(
        x + ((size_t)(b * NN + n1)) * IMG_ELEMS);
    float4* d0 = reinterpret_cast<float4*>(out + (size_t)bj0 * IMG_ELEMS);
    float4* d1 = reinterpret_cast<float4*>(out + (size_t)bj1 * IMG_ELEMS);

    float4 r0[4], r1[4];
#pragma unroll
    for (int i = 0; i < 4; i++) r0[i] = s0[threadIdx.x + i * 256];
#pragma unroll
    for (int i = 0; i < 4; i++) r1[i] = s1[threadIdx.x + i * 256];
#pragma unroll
    for (int i = 0; i < 4; i++) d0[threadIdx.x + i * 256] = r0[i];
#pragma unroll
    for (int i = 0; i < 4; i++) d1[threadIdx.x + i * 256] = r1[i];
}

// ---------------------------------------------------------------------------
extern "C" void kernel_launch(void* const* d_in, const int* in_sizes, int n_in,
                              void* d_out, int out_size)
{
    const float* x = (const float*)d_in[0];
    const float* w = (const float*)d_in[1];
    float* out = (float*)d_out;

    const int k = out_size / (BB * IMG_ELEMS);   // = 256

    score_kernel<<<(BB * NN) / 8, 256>>>(x, w, g_scores);
    topk_kernel<<<BB, NN>>>(g_scores, g_order, k);
    gather_kernel<<<(BB * k) / 2, 256>>>(x, g_order, out, k);
}

// round 6
// speedup vs baseline: 1.0398x; 1.0398x over previous
#include <cuda_runtime.h>
#include <cstdint>

// Problem shape (fixed): x:(32,512,64,64) f32, weight:(1,1,3,3), k=256
#define BB 32
#define NN 512
#define HH 64
#define WW 64
#define IMG_ELEMS (HH * WW)          // 4096

// Scratch (no cudaMalloc allowed)
__device__ float2 g_scores[BB * NN];
__device__ int    g_order[BB * NN];

// ---------------------------------------------------------------------------
// Phase 1 (R4 known-good): warp-per-image conv score. Lane li owns cols
// 2li,2li+1. Rows in chunks of 8: all 8 LDG.64 issued before compute (MLP=8).
// Horizontal neighbors via SHFL; vertical 3-tap window in registers.
// grid = B*N/8, block = 256 (8 warps = 8 images).
// ---------------------------------------------------------------------------
__global__ __launch_bounds__(256) void score_kernel(
    const float* __restrict__ x, const float* __restrict__ w,
    float2* __restrict__ scores)
{
    const int li   = threadIdx.x & 31;
    const int img  = blockIdx.x * 8 + (threadIdx.x >> 5);
    const bool tail = (li == 31);                 // cols 62,63: invalid outputs

    const float wc = w[0];   // corners
    const float wE = w[1];   // edges
    const float wm = w[4];   // center

    const float2* b2 = reinterpret_cast<const float2*>(
        x + (size_t)img * IMG_ELEMS) + li;        // 32 float2 per row

    float Ha1[2], Hm1[2], Ha2[2], Hm2[2];
    float s = 0.f, e = 0.f;

    float2 v[8];

    // ---- chunk 0: rows 0..7 (prime with rows 0,1; compute rows 2..7) ----
#pragma unroll
    for (int i = 0; i < 8; i++) v[i] = b2[i * 32];

    {
        float nx = __shfl_down_sync(0xffffffffu, v[0].x, 1);
        float ny = __shfl_down_sync(0xffffffffu, v[0].y, 1);
        Ha2[0] = v[0].x + nx;  Hm2[0] = v[0].y;
        Ha2[1] = v[0].y + ny;  Hm2[1] = nx;
        nx = __shfl_down_sync(0xffffffffu, v[1].x, 1);
        ny = __shfl_down_sync(0xffffffffu, v[1].y, 1);
        Ha1[0] = v[1].x + nx;  Hm1[0] = v[1].y;
        Ha1[1] = v[1].y + ny;  Hm1[1] = nx;
    }

#define DO_ROW(vv)                                                          \
    {                                                                       \
        float nx = __shfl_down_sync(0xffffffffu, (vv).x, 1);                \
        float ny = __shfl_down_sync(0xffffffffu, (vv).y, 1);                \
        float Hac0 = (vv).x + nx, Hmc0 = (vv).y;                            \
        float Hac1 = (vv).y + ny, Hmc1 = nx;                                \
        float s1a = Ha2[0] + Hac0;                                          \
        float s2a = (Hm2[0] + Hmc0) + Ha1[0];                               \
        float vra = fmaf(wc, s1a, fmaf(wE, s2a, wm * Hm1[0]));              \
        float s1b = Ha2[1] + Hac1;                                          \
        float s2b = (Hm2[1] + Hmc1) + Ha1[1];                               \
        float vrb = fmaf(wc, s1b, fmaf(wE, s2b, wm * Hm1[1]));              \
        float row = fabsf(vra) + fabsf(vrb);                                \
        if (tail) row = 0.f;                                                \
        float tt  = __fadd_rn(s, row);                                      \
        e = __fadd_rn(e, __fadd_rn(__fsub_rn(s, tt), row));                 \
        s = tt;                                                             \
        Ha2[0] = Ha1[0]; Hm2[0] = Hm1[0]; Ha1[0] = Hac0; Hm1[0] = Hmc0;     \
        Ha2[1] = Ha1[1]; Hm2[1] = Hm1[1]; Ha1[1] = Hac1; Hm1[1] = Hmc1;     \
    }

#pragma unroll
    for (int i = 2; i < 8; i++) DO_ROW(v[i]);

    // ---- chunks 1..7 ----
    for (int c = 1; c < 8; c++) {
#pragma unroll
        for (int i = 0; i < 8; i++) v[i] = b2[(c * 8 + i) * 32];
#pragma unroll
        for (int i = 0; i < 8; i++) DO_ROW(v[i]);
    }
#undef DO_ROW

    // Full-warp double-float reduction (exact TwoSum)
#pragma unroll
    for (int off = 16; off; off >>= 1) {
        float s2 = __shfl_down_sync(0xffffffffu, s, off);
        float e2 = __shfl_down_sync(0xffffffffu, e, off);
        float tt  = __fadd_rn(s, s2);
        float z   = __fsub_rn(tt, s);
        float err = __fadd_rn(__fsub_rn(s, __fsub_rn(tt, z)), __fsub_rn(s2, z));
        e = __fadd_rn(__fadd_rn(e, e2), err);
        s = tt;
    }

    if (li == 0) {
        float h = __fadd_rn(s, e);
        float l = __fadd_rn(__fsub_rn(s, h), e);
        scores[img] = make_float2(h, l);
    }
}

// ---------------------------------------------------------------------------
// Phase 2: exact top-k ranking per batch (descending, ties -> lower index first)
// ---------------------------------------------------------------------------
__global__ __launch_bounds__(NN) void topk_kernel(
    const float2* __restrict__ scores, int* __restrict__ order, int k)
{
    __shared__ float2 sc[NN];
    const int b = blockIdx.x;
    const int n = threadIdx.x;
    sc[n] = scores[b * NN + n];
    __syncthreads();

    const float2 mine = sc[n];
    int rank = 0;
#pragma unroll 8
    for (int m = 0; m < NN; m++) {
        float2 o = sc[m];
        bool better = (o.x > mine.x) ||
                      (o.x == mine.x && (o.y > mine.y ||
                                         (o.y == mine.y && m < n)));
        rank += better;
    }
    if (rank < k) order[b * k + rank] = n;
}

// ---------------------------------------------------------------------------
// Phase 3: gather, 2 images per 256-thread block. Both index loads up front,
// then all 8 data loads (2 imgs x 4 float4) in flight before any store.
// Stores are streaming (__stcs): output is never re-read, keep L2 for x.
// Blocks reversed so gather hits the x tail still resident in L2.
// grid = B*k/2 blocks.
// ---------------------------------------------------------------------------
__global__ __launch_bounds__(256) void gather_kernel(
    const float* __restrict__ x, const int* __restrict__ order,
    float* __restrict__ out, int k)
{
    const int pair = gridDim.x - 1 - blockIdx.x;  // reversed for L2 reuse
    const int bj0  = pair * 2;
    const int bj1  = bj0 + 1;
    const int n0   = __ldg(&order[bj0]);
    const int n1   = __ldg(&order[bj1]);
    const int b    = bj0 / k;                      // bj0,bj1 same batch (k even)

    const float4* s0 = reinterpret_cast<const float4*>(
        x + ((size_t)(b * NN + n0)) * IMG_ELEMS);
    const float4* s1 = reinterpret_cast<const float4*>(
        x + ((size_t)(b * NN + n1)) * IMG_ELEMS);
    float4* d0 = reinterpret_cast<float4*>(out + (size_t)bj0 * IMG_ELEMS);
    float4* d1 = reinterpret_cast<float4*>(out + (size_t)bj1 * IMG_ELEMS);

    float4 r0[4], r1[4];
#pragma unroll
    for (int i = 0; i < 4; i++) r0[i] = s0[threadIdx.x + i * 256];
#pragma unroll
    for (int i = 0; i < 4; i++) r1[i] = s1[threadIdx.x + i * 256];
#pragma unroll
    for (int i = 0; i < 4; i++) __stcs(&d0[threadIdx.x + i * 256], r0[i]);
#pragma unroll
    for (int i = 0; i < 4; i++) __stcs(&d1[threadIdx.x + i * 256], r1[i]);
}

// ---------------------------------------------------------------------------
extern "C" void kernel_launch(void* const* d_in, const int* in_sizes, int n_in,
                              void* d_out, int out_size)
{
    const float* x = (const float*)d_in[0];
    const float* w = (const float*)d_in[1];
    float* out = (float*)d_out;

    const int k = out_size / (BB * IMG_ELEMS);   // = 256

    score_kernel<<<(BB * NN) / 8, 256>>>(x, w, g_scores);
    topk_kernel<<<BB, NN>>>(g_scores, g_order, k);
    gather_kernel<<<(BB * k) / 2, 256>>>(x, g_order, out, k);
}